// round 4
// baseline (speedup 1.0000x reference)
#include <cuda_runtime.h>
#include <cuda_bf16.h>
#include <math.h>

#define S_LEN 2048
#define HID   2048
#define NH    16
#define NKV   4
#define HD    128
#define KVH   (NKV*HD)   // 512

// Scratch (no allocations allowed): Q 16MB, K 4MB, V 4MB, attn-out 16MB
__device__ float g_q[S_LEN * HID];
__device__ float g_k[S_LEN * KVH];
__device__ float g_v[S_LEN * KVH];
__device__ float g_o[S_LEN * HID];

// ---------------------------------------------------------------------------
// SGEMM: C[M,N] = A[M,K] @ B[N,K]^T + bias[N]   (both operands K-contiguous)
// 128x128 block, BK=8, 8x8 per-thread microtile, 256 threads.
// ---------------------------------------------------------------------------
__global__ __launch_bounds__(256) void sgemm_nt(
    const float* __restrict__ A, const float* __restrict__ B,
    const float* __restrict__ bias, float* __restrict__ C,
    int M, int N, int K)
{
    __shared__ float As[8][128];
    __shared__ float Bs[8][128];

    const int tid  = threadIdx.x;
    const int bm   = blockIdx.y * 128;
    const int bn   = blockIdx.x * 128;
    const int lrow = tid >> 1;          // 0..127
    const int lk4  = (tid & 1) * 4;     // 0 or 4
    const int ty   = tid >> 4;          // 0..15 -> rows ty*8..
    const int tx   = tid & 15;          // 0..15 -> cols tx*8..

    const float* Aptr = A + (size_t)(bm + lrow) * K + lk4;
    const float* Bptr = B + (size_t)(bn + lrow) * K + lk4;

    float acc[8][8];
#pragma unroll
    for (int i = 0; i < 8; i++)
#pragma unroll
        for (int j = 0; j < 8; j++) acc[i][j] = 0.f;

    for (int k0 = 0; k0 < K; k0 += 8) {
        float4 a4 = *(const float4*)(Aptr + k0);
        float4 b4 = *(const float4*)(Bptr + k0);
        As[lk4 + 0][lrow] = a4.x; As[lk4 + 1][lrow] = a4.y;
        As[lk4 + 2][lrow] = a4.z; As[lk4 + 3][lrow] = a4.w;
        Bs[lk4 + 0][lrow] = b4.x; Bs[lk4 + 1][lrow] = b4.y;
        Bs[lk4 + 2][lrow] = b4.z; Bs[lk4 + 3][lrow] = b4.w;
        __syncthreads();

#pragma unroll
        for (int kk = 0; kk < 8; kk++) {
            float ar[8], br[8];
            *(float4*)(ar)     = *(float4*)&As[kk][ty * 8];
            *(float4*)(ar + 4) = *(float4*)&As[kk][ty * 8 + 4];
            *(float4*)(br)     = *(float4*)&Bs[kk][tx * 8];
            *(float4*)(br + 4) = *(float4*)&Bs[kk][tx * 8 + 4];
#pragma unroll
            for (int i = 0; i < 8; i++)
#pragma unroll
                for (int j = 0; j < 8; j++)
                    acc[i][j] += ar[i] * br[j];
        }
        __syncthreads();
    }

    float breg[8];
#pragma unroll
    for (int j = 0; j < 8; j++)
        breg[j] = bias ? bias[bn + tx * 8 + j] : 0.f;

#pragma unroll
    for (int i = 0; i < 8; i++) {
        const size_t row = (size_t)(bm + ty * 8 + i);
        float4 o0, o1;
        o0.x = acc[i][0] + breg[0]; o0.y = acc[i][1] + breg[1];
        o0.z = acc[i][2] + breg[2]; o0.w = acc[i][3] + breg[3];
        o1.x = acc[i][4] + breg[4]; o1.y = acc[i][5] + breg[5];
        o1.z = acc[i][6] + breg[6]; o1.w = acc[i][7] + breg[7];
        *(float4*)&C[row * N + bn + tx * 8]     = o0;
        *(float4*)&C[row * N + bn + tx * 8 + 4] = o1;
    }
}

// ---------------------------------------------------------------------------
// RoPE in-place on [S, nheads*128] buffer. One thread per (s, head, i<64).
// position_ids is INT32 (JAX x64-disabled downcasts the declared int64).
// ---------------------------------------------------------------------------
__global__ void rope_kernel(float* __restrict__ buf,
                            const int* __restrict__ pos_ids,
                            int nheads, int row_stride, int total)
{
    int idx = blockIdx.x * blockDim.x + threadIdx.x;
    if (idx >= total) return;
    int i = idx & 63;
    int h = (idx >> 6) % nheads;
    int s = idx / (64 * nheads);

    float pos = (float)pos_ids[s];
    // inv_freq = 10000^(-2i/128) computed via expf (accurate, NOT __powf)
    float inv = expf(-(float)(2 * i) * (1.0f / 128.0f) * 9.210340371976184f);
    float ang = pos * inv;
    float c, sn;
    sincosf(ang, &sn, &c);

    float* p = buf + (size_t)s * row_stride + h * HD;
    float lo = p[i], hi = p[i + 64];
    p[i]      = lo * c - hi * sn;
    p[i + 64] = hi * c + lo * sn;
}

// ---------------------------------------------------------------------------
// Flash attention (causal, GQA 4:1), fp32.
// Block = (qtile of 64 rows, head). 256 threads as 16(ty=rowgrp) x 16(tx).
// Each thread: 4 rows x (4 score cols | 8 out dims).
// ---------------------------------------------------------------------------
__global__ __launch_bounds__(256) void flash_kernel(
    const float* __restrict__ Q, const float* __restrict__ Km,
    const float* __restrict__ Vm, float* __restrict__ O)
{
    extern __shared__ float sm[];
    float* Qs  = sm;                 // [64][128]
    float* Kst = sm + 64 * 128;      // [128][64]  (transposed: [k][col])
    float* Vs  = Kst + 128 * 64;     // [64][128]
    float* Ps  = Vs + 64 * 128;      // [64][64]

    const int h   = blockIdx.y;
    const int qt  = blockIdx.x;
    const int kvh = h >> 2;
    const int tid = threadIdx.x;
    const int ty  = tid >> 4;
    const int tx  = tid & 15;
    const int q0  = qt * 64;

    for (int e = tid; e < 64 * 32; e += 256) {
        int r = e >> 5, d4 = (e & 31) << 2;
        *(float4*)&Qs[r * 128 + d4] =
            *(const float4*)&Q[(size_t)(q0 + r) * HID + h * HD + d4];
    }

    float acc[4][8];
    float m_i[4], l_i[4];
#pragma unroll
    for (int r = 0; r < 4; r++) {
        m_i[r] = -1e30f; l_i[r] = 0.f;
#pragma unroll
        for (int d = 0; d < 8; d++) acc[r][d] = 0.f;
    }
    const float scale = 0.08838834764831845f;   // 1/sqrt(128)

    for (int t = 0; t <= qt; t++) {
        __syncthreads();
        const int j0 = t * 64;
        for (int e = tid; e < 64 * 32; e += 256) {
            int r = e >> 5, d4 = (e & 31) << 2;
            float4 kk = *(const float4*)&Km[(size_t)(j0 + r) * KVH + kvh * HD + d4];
            Kst[(d4 + 0) * 64 + r] = kk.x;
            Kst[(d4 + 1) * 64 + r] = kk.y;
            Kst[(d4 + 2) * 64 + r] = kk.z;
            Kst[(d4 + 3) * 64 + r] = kk.w;
            *(float4*)&Vs[r * 128 + d4] =
                *(const float4*)&Vm[(size_t)(j0 + r) * KVH + kvh * HD + d4];
        }
        __syncthreads();

        // -------- scores: 4 rows x 4 cols --------
        float sc[4][4];
#pragma unroll
        for (int r = 0; r < 4; r++)
#pragma unroll
            for (int c = 0; c < 4; c++) sc[r][c] = 0.f;

        for (int k = 0; k < 128; k += 4) {
            float kc[4][4];
            *(float4*)kc[0] = *(float4*)&Kst[(k + 0) * 64 + tx * 4];
            *(float4*)kc[1] = *(float4*)&Kst[(k + 1) * 64 + tx * 4];
            *(float4*)kc[2] = *(float4*)&Kst[(k + 2) * 64 + tx * 4];
            *(float4*)kc[3] = *(float4*)&Kst[(k + 3) * 64 + tx * 4];
#pragma unroll
            for (int r = 0; r < 4; r++) {
                float4 q4 = *(float4*)&Qs[(ty * 4 + r) * 128 + k];
#pragma unroll
                for (int c = 0; c < 4; c++) {
                    sc[r][c] += q4.x * kc[0][c] + q4.y * kc[1][c]
                              + q4.z * kc[2][c] + q4.w * kc[3][c];
                }
            }
        }

#pragma unroll
        for (int r = 0; r < 4; r++)
#pragma unroll
            for (int c = 0; c < 4; c++) sc[r][c] *= scale;

        if (t == qt) {   // diagonal tile: causal mask j > i
#pragma unroll
            for (int r = 0; r < 4; r++)
#pragma unroll
                for (int c = 0; c < 4; c++)
                    if (j0 + tx * 4 + c > q0 + ty * 4 + r) sc[r][c] = -1e30f;
        }

        // -------- online softmax (row reduction across 16 tx lanes) --------
#pragma unroll
        for (int r = 0; r < 4; r++) {
            float rmax = fmaxf(fmaxf(sc[r][0], sc[r][1]), fmaxf(sc[r][2], sc[r][3]));
#pragma unroll
            for (int o = 1; o < 16; o <<= 1)
                rmax = fmaxf(rmax, __shfl_xor_sync(0xffffffffu, rmax, o));
            float mnew  = fmaxf(m_i[r], rmax);
            float alpha = __expf(m_i[r] - mnew);
            float p0 = __expf(sc[r][0] - mnew);
            float p1 = __expf(sc[r][1] - mnew);
            float p2 = __expf(sc[r][2] - mnew);
            float p3 = __expf(sc[r][3] - mnew);
            float psum = p0 + p1 + p2 + p3;
#pragma unroll
            for (int o = 1; o < 16; o <<= 1)
                psum += __shfl_xor_sync(0xffffffffu, psum, o);
            l_i[r] = l_i[r] * alpha + psum;
            m_i[r] = mnew;
#pragma unroll
            for (int d = 0; d < 8; d++) acc[r][d] *= alpha;
            Ps[(ty * 4 + r) * 64 + tx * 4 + 0] = p0;
            Ps[(ty * 4 + r) * 64 + tx * 4 + 1] = p1;
            Ps[(ty * 4 + r) * 64 + tx * 4 + 2] = p2;
            Ps[(ty * 4 + r) * 64 + tx * 4 + 3] = p3;
        }
        __syncthreads();

        // -------- PV: acc[r][d] += sum_c P[row][c] * V[c][dim] --------
#pragma unroll 4
        for (int c = 0; c < 64; c++) {
            float4 v0 = *(float4*)&Vs[c * 128 + tx * 8];
            float4 v1 = *(float4*)&Vs[c * 128 + tx * 8 + 4];
#pragma unroll
            for (int r = 0; r < 4; r++) {
                float p = Ps[(ty * 4 + r) * 64 + c];
                acc[r][0] += p * v0.x; acc[r][1] += p * v0.y;
                acc[r][2] += p * v0.z; acc[r][3] += p * v0.w;
                acc[r][4] += p * v1.x; acc[r][5] += p * v1.y;
                acc[r][6] += p * v1.z; acc[r][7] += p * v1.w;
            }
        }
    }

    // -------- normalize + write [s][h*128+dim] --------
#pragma unroll
    for (int r = 0; r < 4; r++) {
        float inv = 1.0f / l_i[r];
        float4 o0, o1;
        o0.x = acc[r][0] * inv; o0.y = acc[r][1] * inv;
        o0.z = acc[r][2] * inv; o0.w = acc[r][3] * inv;
        o1.x = acc[r][4] * inv; o1.y = acc[r][5] * inv;
        o1.z = acc[r][6] * inv; o1.w = acc[r][7] * inv;
        size_t base = (size_t)(q0 + ty * 4 + r) * HID + h * HD + tx * 8;
        *(float4*)&O[base]     = o0;
        *(float4*)&O[base + 4] = o1;
    }
}

// ---------------------------------------------------------------------------

extern "C" void kernel_launch(void* const* d_in, const int* in_sizes, int n_in,
                              void* d_out, int out_size)
{
    const float*     x    = (const float*)d_in[0];
    /* d_in[1] = attention_mask: exact causal triu(-inf), applied analytically */
    const int*       pos  = (const int*)d_in[2];   // int32 (JAX x64 disabled)
    const float*     wq   = (const float*)d_in[3];
    const float*     bq   = (const float*)d_in[4];
    const float*     wk   = (const float*)d_in[5];
    const float*     bk   = (const float*)d_in[6];
    const float*     wv   = (const float*)d_in[7];
    const float*     bv   = (const float*)d_in[8];
    const float*     wo   = (const float*)d_in[9];
    float*           out  = (float*)d_out;

    float *qp, *kp, *vp, *op;
    cudaGetSymbolAddress((void**)&qp, g_q);
    cudaGetSymbolAddress((void**)&kp, g_k);
    cudaGetSymbolAddress((void**)&vp, g_v);
    cudaGetSymbolAddress((void**)&op, g_o);

    // QKV projections
    sgemm_nt<<<dim3(HID / 128, S_LEN / 128), 256>>>(x, wq, bq, qp, S_LEN, HID, HID);
    sgemm_nt<<<dim3(KVH / 128, S_LEN / 128), 256>>>(x, wk, bk, kp, S_LEN, KVH, HID);
    sgemm_nt<<<dim3(KVH / 128, S_LEN / 128), 256>>>(x, wv, bv, vp, S_LEN, KVH, HID);

    // RoPE on Q (16 heads) and K (4 heads)
    {
        int totq = S_LEN * NH * 64;
        rope_kernel<<<(totq + 255) / 256, 256>>>(qp, pos, NH, HID, totq);
        int totk = S_LEN * NKV * 64;
        rope_kernel<<<(totk + 255) / 256, 256>>>(kp, pos, NKV, KVH, totk);
    }

    // Flash attention
    {
        const int smem = (64 * 128 + 128 * 64 + 64 * 128 + 64 * 64) * (int)sizeof(float); // 114688
        cudaFuncSetAttribute(flash_kernel, cudaFuncAttributeMaxDynamicSharedMemorySize, smem);
        flash_kernel<<<dim3(S_LEN / 64, NH), 256, smem>>>(qp, kp, vp, op);
    }

    // Output projection
    sgemm_nt<<<dim3(HID / 128, S_LEN / 128), 256>>>(op, wo, nullptr, out, S_LEN, HID, HID);
}

// round 5
// speedup vs baseline: 3.2141x; 3.2141x over previous
#include <cuda_runtime.h>
#include <cuda_bf16.h>
#include <math.h>
#include <stdint.h>

#define S_LEN 2048
#define HID   2048
#define NH    16
#define NKV   4
#define HD    128
#define KVH   512

__device__ float g_q[S_LEN * HID];
__device__ float g_k[S_LEN * KVH];
__device__ float g_v[S_LEN * KVH];
__device__ float g_o[S_LEN * HID];

__device__ __forceinline__ uint32_t smem_u32(const void* p) {
    return (uint32_t)__cvta_generic_to_shared(p);
}

#define MMA_BF16(c, a0, a1, a2, a3, b0, b1)                                 \
    asm("mma.sync.aligned.m16n8k16.row.col.f32.bf16.bf16.f32 "              \
        "{%0,%1,%2,%3},{%4,%5,%6,%7},{%8,%9},{%0,%1,%2,%3};"                \
        : "+f"(c[0]), "+f"(c[1]), "+f"(c[2]), "+f"(c[3])                    \
        : "r"(a0), "r"(a1), "r"(a2), "r"(a3), "r"(b0), "r"(b1))

#define LDSM_X4(r0, r1, r2, r3, addr)                                       \
    asm("ldmatrix.sync.aligned.m8n8.x4.shared.b16 {%0,%1,%2,%3},[%4];"      \
        : "=r"(r0), "=r"(r1), "=r"(r2), "=r"(r3) : "r"(addr))

#define LDSM_X2(r0, r1, addr)                                               \
    asm("ldmatrix.sync.aligned.m8n8.x2.shared.b16 {%0,%1},[%2];"            \
        : "=r"(r0), "=r"(r1) : "r"(addr))

#define LDSM_X2T(r0, r1, addr)                                              \
    asm("ldmatrix.sync.aligned.m8n8.x2.trans.shared.b16 {%0,%1},[%2];"      \
        : "=r"(r0), "=r"(r1) : "r"(addr))

// fp32 -> (hi, lo) bf16 split, 4 consecutive elements, stored to smem
__device__ __forceinline__ void split_store4(__nv_bfloat16* hi, __nv_bfloat16* lo,
                                             int idx, float4 v)
{
    __nv_bfloat162 h01, h23, l01, l23;
    h01.x = __float2bfloat16(v.x); h01.y = __float2bfloat16(v.y);
    h23.x = __float2bfloat16(v.z); h23.y = __float2bfloat16(v.w);
    l01.x = __float2bfloat16(v.x - __bfloat162float(h01.x));
    l01.y = __float2bfloat16(v.y - __bfloat162float(h01.y));
    l23.x = __float2bfloat16(v.z - __bfloat162float(h23.x));
    l23.y = __float2bfloat16(v.w - __bfloat162float(h23.y));
    *(__nv_bfloat162*)&hi[idx]     = h01;
    *(__nv_bfloat162*)&hi[idx + 2] = h23;
    *(__nv_bfloat162*)&lo[idx]     = l01;
    *(__nv_bfloat162*)&lo[idx + 2] = l23;
}

__device__ __forceinline__ uint32_t pack2_hi(float x, float y) {
    __nv_bfloat162 t;
    t.x = __float2bfloat16(x); t.y = __float2bfloat16(y);
    return *(uint32_t*)&t;
}
__device__ __forceinline__ uint32_t pack2_lo(float x, float y) {
    __nv_bfloat162 t;
    t.x = __float2bfloat16(x - __bfloat162float(__float2bfloat16(x)));
    t.y = __float2bfloat16(y - __bfloat162float(__float2bfloat16(y)));
    return *(uint32_t*)&t;
}

// ---------------------------------------------------------------------------
// Tensor-core GEMM with bf16 split (3-term): C[M,N] = A[M,K] @ B[N,K]^T + bias
// Block 128x128, BK=32, 8 warps (2M x 4N), warp tile 64x32.
// ---------------------------------------------------------------------------
__global__ __launch_bounds__(256) void gemm_bf16s(
    const float* __restrict__ A, const float* __restrict__ B,
    const float* __restrict__ bias, float* __restrict__ C,
    int M, int N, int K)
{
    const int LDS_ = 40;   // 32 + 8 pad (bf16 elems)
    __shared__ __nv_bfloat16 Ah[128 * 40], Al[128 * 40];
    __shared__ __nv_bfloat16 Bh[128 * 40], Bl[128 * 40];

    const int tid  = threadIdx.x;
    const int bm   = blockIdx.y * 128, bn = blockIdx.x * 128;
    const int warp = tid >> 5, lane = tid & 31;
    const int wm   = (warp & 1) * 64;
    const int wn   = (warp >> 1) * 32;
    const int g    = lane >> 2, t2 = (lane & 3) * 2;

    const int lrow = tid >> 3;        // 0..31
    const int lcol = (tid & 7) * 4;   // float4 col in 32-wide chunk

    float acc[4][4][4];
#pragma unroll
    for (int mi = 0; mi < 4; mi++)
#pragma unroll
        for (int ni = 0; ni < 4; ni++)
#pragma unroll
            for (int q = 0; q < 4; q++) acc[mi][ni][q] = 0.f;

    float4 aReg[4], bReg[4];
#pragma unroll
    for (int rr = 0; rr < 4; rr++) {
        aReg[rr] = *(const float4*)&A[(size_t)(bm + lrow + rr * 32) * K + lcol];
        bReg[rr] = *(const float4*)&B[(size_t)(bn + lrow + rr * 32) * K + lcol];
    }

    const int arow = (lane & 7) + ((lane & 8) ? 8 : 0);
    const int brow = lane & 7;

    for (int k0 = 0; k0 < K; k0 += 32) {
        __syncthreads();
#pragma unroll
        for (int rr = 0; rr < 4; rr++) {
            split_store4(Ah, Al, (lrow + rr * 32) * LDS_ + lcol, aReg[rr]);
            split_store4(Bh, Bl, (lrow + rr * 32) * LDS_ + lcol, bReg[rr]);
        }
        __syncthreads();

        if (k0 + 32 < K) {
#pragma unroll
            for (int rr = 0; rr < 4; rr++) {
                aReg[rr] = *(const float4*)&A[(size_t)(bm + lrow + rr * 32) * K + k0 + 32 + lcol];
                bReg[rr] = *(const float4*)&B[(size_t)(bn + lrow + rr * 32) * K + k0 + 32 + lcol];
            }
        }

#pragma unroll
        for (int kt = 0; kt < 32; kt += 16) {
            const int acol = kt + ((lane & 16) ? 8 : 0);
            uint32_t ah[4][4], al[4][4];
#pragma unroll
            for (int mi = 0; mi < 4; mi++) {
                LDSM_X4(ah[mi][0], ah[mi][1], ah[mi][2], ah[mi][3],
                        smem_u32(&Ah[(wm + mi * 16 + arow) * LDS_ + acol]));
                LDSM_X4(al[mi][0], al[mi][1], al[mi][2], al[mi][3],
                        smem_u32(&Al[(wm + mi * 16 + arow) * LDS_ + acol]));
            }
            const int bcol = kt + ((lane & 8) ? 8 : 0);
#pragma unroll
            for (int ni = 0; ni < 4; ni++) {
                uint32_t bh0, bh1, bl0, bl1;
                LDSM_X2(bh0, bh1, smem_u32(&Bh[(wn + ni * 8 + brow) * LDS_ + bcol]));
                LDSM_X2(bl0, bl1, smem_u32(&Bl[(wn + ni * 8 + brow) * LDS_ + bcol]));
#pragma unroll
                for (int mi = 0; mi < 4; mi++) {
                    MMA_BF16(acc[mi][ni], ah[mi][0], ah[mi][1], ah[mi][2], ah[mi][3], bh0, bh1);
                    MMA_BF16(acc[mi][ni], ah[mi][0], ah[mi][1], ah[mi][2], ah[mi][3], bl0, bl1);
                    MMA_BF16(acc[mi][ni], al[mi][0], al[mi][1], al[mi][2], al[mi][3], bh0, bh1);
                }
            }
        }
    }

#pragma unroll
    for (int mi = 0; mi < 4; mi++) {
#pragma unroll
        for (int ni = 0; ni < 4; ni++) {
            const int row = bm + wm + mi * 16 + g;
            const int col = bn + wn + ni * 8 + t2;
            float bb0 = bias ? bias[col] : 0.f;
            float bb1 = bias ? bias[col + 1] : 0.f;
            float2 v0; v0.x = acc[mi][ni][0] + bb0; v0.y = acc[mi][ni][1] + bb1;
            float2 v1; v1.x = acc[mi][ni][2] + bb0; v1.y = acc[mi][ni][3] + bb1;
            *(float2*)&C[(size_t)row * N + col]       = v0;
            *(float2*)&C[(size_t)(row + 8) * N + col] = v1;
        }
    }
}

// ---------------------------------------------------------------------------
// RoPE in-place (position_ids are int32)
// ---------------------------------------------------------------------------
__global__ void rope_kernel(float* __restrict__ buf,
                            const int* __restrict__ pos_ids,
                            int nheads, int row_stride, int total)
{
    int idx = blockIdx.x * blockDim.x + threadIdx.x;
    if (idx >= total) return;
    int i = idx & 63;
    int h = (idx >> 6) % nheads;
    int s = idx / (64 * nheads);

    float pos = (float)pos_ids[s];
    float inv = expf(-(float)(2 * i) * (1.0f / 128.0f) * 9.210340371976184f);
    float ang = pos * inv;
    float c, sn;
    sincosf(ang, &sn, &c);

    float* p = buf + (size_t)s * row_stride + h * HD;
    float lo = p[i], hi = p[i + 64];
    p[i]      = lo * c - hi * sn;
    p[i + 64] = hi * c + lo * sn;
}

// ---------------------------------------------------------------------------
// Flash attention, tensor-core, bf16-split. Causal, GQA 4:1.
// Block: 128 q-rows x one head, 256 threads (8 warps x 16 rows), KV tile 64.
// ---------------------------------------------------------------------------
__global__ __launch_bounds__(256) void flash_mma(
    const float* __restrict__ Q, const float* __restrict__ Km,
    const float* __restrict__ Vm, float* __restrict__ O)
{
    extern __shared__ __nv_bfloat16 sm[];
    const int LQ = 136, LK = 136;
    __nv_bfloat16* Qh = sm;
    __nv_bfloat16* Ql = Qh + 128 * LQ;
    __nv_bfloat16* Kh = Ql + 128 * LQ;
    __nv_bfloat16* Kl = Kh + 64 * LK;
    __nv_bfloat16* Vh = Kl + 64 * LK;
    __nv_bfloat16* Vl = Vh + 64 * LK;

    const int h   = blockIdx.y;
    const int qt  = blockIdx.x;
    const int q0  = qt * 128;
    const int kvh = h >> 2;
    const int tid = threadIdx.x, warp = tid >> 5, lane = tid & 31;
    const int g   = lane >> 2, t2 = (lane & 3) * 2;

    // load + split Q tile [128][128]
    for (int e = tid; e < 128 * 32; e += 256) {
        int r = e >> 5, c4 = (e & 31) << 2;
        float4 v = *(const float4*)&Q[(size_t)(q0 + r) * HID + h * HD + c4];
        split_store4(Qh, Ql, r * LQ + c4, v);
    }

    float m0 = -1e30f, m1 = -1e30f, l0 = 0.f, l1 = 0.f;
    float oacc[16][4];
#pragma unroll
    for (int nf = 0; nf < 16; nf++)
#pragma unroll
        for (int q = 0; q < 4; q++) oacc[nf][q] = 0.f;

    const float scale = 0.08838834764831845f;   // 1/sqrt(128)
    const int mrow = warp * 16;
    const int r0 = q0 + mrow + g, r1 = r0 + 8;
    const int wmax = q0 + mrow + 15;
    const int arow = (lane & 7) + ((lane & 8) ? 8 : 0);
    const int brow = lane & 7;
    const int vrow = lane & 15;

    const int ntiles = 2 * qt + 2;
    for (int t = 0; t < ntiles; t++) {
        const int j0 = t * 64;
        __syncthreads();
        for (int e = tid; e < 64 * 32; e += 256) {
            int r = e >> 5, c4 = (e & 31) << 2;
            float4 kk = *(const float4*)&Km[(size_t)(j0 + r) * KVH + kvh * HD + c4];
            split_store4(Kh, Kl, r * LK + c4, kk);
            float4 vv = *(const float4*)&Vm[(size_t)(j0 + r) * KVH + kvh * HD + c4];
            split_store4(Vh, Vl, r * LK + c4, vv);
        }
        __syncthreads();
        if (j0 > wmax) continue;   // tile fully masked for this warp

        // ---- S = Q K^T (warp: 16 rows x 64 kv) ----
        float s[8][4];
#pragma unroll
        for (int nf = 0; nf < 8; nf++)
#pragma unroll
            for (int q = 0; q < 4; q++) s[nf][q] = 0.f;

#pragma unroll
        for (int kt = 0; kt < 128; kt += 16) {
            const int acol = kt + ((lane & 16) ? 8 : 0);
            uint32_t qh[4], ql[4];
            LDSM_X4(qh[0], qh[1], qh[2], qh[3], smem_u32(&Qh[(mrow + arow) * LQ + acol]));
            LDSM_X4(ql[0], ql[1], ql[2], ql[3], smem_u32(&Ql[(mrow + arow) * LQ + acol]));
            const int bcol = kt + ((lane & 8) ? 8 : 0);
#pragma unroll
            for (int nf = 0; nf < 8; nf++) {
                uint32_t bh0, bh1, bl0, bl1;
                LDSM_X2(bh0, bh1, smem_u32(&Kh[(nf * 8 + brow) * LK + bcol]));
                LDSM_X2(bl0, bl1, smem_u32(&Kl[(nf * 8 + brow) * LK + bcol]));
                MMA_BF16(s[nf], qh[0], qh[1], qh[2], qh[3], bh0, bh1);
                MMA_BF16(s[nf], qh[0], qh[1], qh[2], qh[3], bl0, bl1);
                MMA_BF16(s[nf], ql[0], ql[1], ql[2], ql[3], bh0, bh1);
            }
        }

        // ---- scale + causal mask ----
#pragma unroll
        for (int nf = 0; nf < 8; nf++) {
#pragma unroll
            for (int q = 0; q < 4; q++) s[nf][q] *= scale;
        }
        if (j0 + 63 > r0) {
#pragma unroll
            for (int nf = 0; nf < 8; nf++) {
                const int c0 = j0 + nf * 8 + t2;
                if (c0     > r0) s[nf][0] = -1e30f;
                if (c0 + 1 > r0) s[nf][1] = -1e30f;
                if (c0     > r1) s[nf][2] = -1e30f;
                if (c0 + 1 > r1) s[nf][3] = -1e30f;
            }
        }

        // ---- online softmax (2 rows per thread; quad shares a row) ----
        float mx0 = -1e30f, mx1 = -1e30f;
#pragma unroll
        for (int nf = 0; nf < 8; nf++) {
            mx0 = fmaxf(mx0, fmaxf(s[nf][0], s[nf][1]));
            mx1 = fmaxf(mx1, fmaxf(s[nf][2], s[nf][3]));
        }
        mx0 = fmaxf(mx0, __shfl_xor_sync(0xffffffffu, mx0, 1));
        mx0 = fmaxf(mx0, __shfl_xor_sync(0xffffffffu, mx0, 2));
        mx1 = fmaxf(mx1, __shfl_xor_sync(0xffffffffu, mx1, 1));
        mx1 = fmaxf(mx1, __shfl_xor_sync(0xffffffffu, mx1, 2));
        const float mn0 = fmaxf(m0, mx0), mn1 = fmaxf(m1, mx1);
        const float a0 = __expf(m0 - mn0), a1 = __expf(m1 - mn1);
        float sum0 = 0.f, sum1 = 0.f;
#pragma unroll
        for (int nf = 0; nf < 8; nf++) {
            s[nf][0] = __expf(s[nf][0] - mn0);
            s[nf][1] = __expf(s[nf][1] - mn0);
            s[nf][2] = __expf(s[nf][2] - mn1);
            s[nf][3] = __expf(s[nf][3] - mn1);
            sum0 += s[nf][0] + s[nf][1];
            sum1 += s[nf][2] + s[nf][3];
        }
        sum0 += __shfl_xor_sync(0xffffffffu, sum0, 1);
        sum0 += __shfl_xor_sync(0xffffffffu, sum0, 2);
        sum1 += __shfl_xor_sync(0xffffffffu, sum1, 1);
        sum1 += __shfl_xor_sync(0xffffffffu, sum1, 2);
        l0 = l0 * a0 + sum0;  l1 = l1 * a1 + sum1;
        m0 = mn0;             m1 = mn1;
#pragma unroll
        for (int nf = 0; nf < 16; nf++) {
            oacc[nf][0] *= a0; oacc[nf][1] *= a0;
            oacc[nf][2] *= a1; oacc[nf][3] *= a1;
        }

        // ---- pack P fragments (C layout == A layout) ----
        uint32_t pah[4][4], pal[4][4];
#pragma unroll
        for (int j = 0; j < 4; j++) {
            pah[j][0] = pack2_hi(s[2*j][0],   s[2*j][1]);
            pah[j][1] = pack2_hi(s[2*j][2],   s[2*j][3]);
            pah[j][2] = pack2_hi(s[2*j+1][0], s[2*j+1][1]);
            pah[j][3] = pack2_hi(s[2*j+1][2], s[2*j+1][3]);
            pal[j][0] = pack2_lo(s[2*j][0],   s[2*j][1]);
            pal[j][1] = pack2_lo(s[2*j][2],   s[2*j][3]);
            pal[j][2] = pack2_lo(s[2*j+1][0], s[2*j+1][1]);
            pal[j][3] = pack2_lo(s[2*j+1][2], s[2*j+1][3]);
        }

        // ---- O += P @ V  (V fragments via ldmatrix.trans from [kv][dim]) ----
#pragma unroll
        for (int j = 0; j < 4; j++) {
#pragma unroll
            for (int nf = 0; nf < 16; nf++) {
                uint32_t bh0, bh1, bl0, bl1;
                LDSM_X2T(bh0, bh1, smem_u32(&Vh[(16 * j + vrow) * LK + nf * 8]));
                LDSM_X2T(bl0, bl1, smem_u32(&Vl[(16 * j + vrow) * LK + nf * 8]));
                MMA_BF16(oacc[nf], pah[j][0], pah[j][1], pah[j][2], pah[j][3], bh0, bh1);
                MMA_BF16(oacc[nf], pah[j][0], pah[j][1], pah[j][2], pah[j][3], bl0, bl1);
                MMA_BF16(oacc[nf], pal[j][0], pal[j][1], pal[j][2], pal[j][3], bh0, bh1);
            }
        }
    }

    // ---- normalize + store ----
    const float inv0 = 1.f / l0, inv1 = 1.f / l1;
#pragma unroll
    for (int nf = 0; nf < 16; nf++) {
        const int col = h * HD + nf * 8 + t2;
        float2 v0; v0.x = oacc[nf][0] * inv0; v0.y = oacc[nf][1] * inv0;
        float2 v1; v1.x = oacc[nf][2] * inv1; v1.y = oacc[nf][3] * inv1;
        *(float2*)&O[(size_t)r0 * HID + col] = v0;
        *(float2*)&O[(size_t)r1 * HID + col] = v1;
    }
}

// ---------------------------------------------------------------------------

extern "C" void kernel_launch(void* const* d_in, const int* in_sizes, int n_in,
                              void* d_out, int out_size)
{
    const float* x   = (const float*)d_in[0];
    /* d_in[1] attention_mask: exact causal triu(-inf), applied analytically */
    const int*   pos = (const int*)d_in[2];
    const float* wq  = (const float*)d_in[3];
    const float* bq  = (const float*)d_in[4];
    const float* wk  = (const float*)d_in[5];
    const float* bk  = (const float*)d_in[6];
    const float* wv  = (const float*)d_in[7];
    const float* bv  = (const float*)d_in[8];
    const float* wo  = (const float*)d_in[9];
    float*       out = (float*)d_out;

    float *qp, *kp, *vp, *op;
    cudaGetSymbolAddress((void**)&qp, g_q);
    cudaGetSymbolAddress((void**)&kp, g_k);
    cudaGetSymbolAddress((void**)&vp, g_v);
    cudaGetSymbolAddress((void**)&op, g_o);

    // QKV projections (tensor core)
    gemm_bf16s<<<dim3(HID / 128, S_LEN / 128), 256>>>(x, wq, bq, qp, S_LEN, HID, HID);
    gemm_bf16s<<<dim3(KVH / 128, S_LEN / 128), 256>>>(x, wk, bk, kp, S_LEN, KVH, HID);
    gemm_bf16s<<<dim3(KVH / 128, S_LEN / 128), 256>>>(x, wv, bv, vp, S_LEN, KVH, HID);

    // RoPE
    {
        int totq = S_LEN * NH * 64;
        rope_kernel<<<(totq + 255) / 256, 256>>>(qp, pos, NH, HID, totq);
        int totk = S_LEN * NKV * 64;
        rope_kernel<<<(totk + 255) / 256, 256>>>(kp, pos, NKV, KVH, totk);
    }

    // Flash attention (tensor core)
    {
        const int smem = (2 * 128 * 136 + 4 * 64 * 136) * (int)sizeof(__nv_bfloat16); // 139264
        cudaFuncSetAttribute(flash_mma, cudaFuncAttributeMaxDynamicSharedMemorySize, smem);
        flash_mma<<<dim3(S_LEN / 128, NH), 256, smem>>>(qp, kp, vp, op);
    }

    // Output projection
    gemm_bf16s<<<dim3(HID / 128, S_LEN / 128), 256>>>(op, wo, nullptr, out, S_LEN, HID, HID);
}

// round 7
// speedup vs baseline: 3.4788x; 1.0824x over previous
#include <cuda_runtime.h>
#include <cuda_bf16.h>
#include <math.h>
#include <stdint.h>

#define S_LEN 2048
#define HID   2048
#define NH    16
#define NKV   4
#define HD    128
#define KVH   512

typedef __nv_bfloat16 bf16;

// ------------------- split-plane scratch (bf16 hi/lo) -------------------
__device__ bf16 g_xh[S_LEN * HID], g_xl[S_LEN * HID];
__device__ bf16 g_wqh[HID * HID],  g_wql[HID * HID];
__device__ bf16 g_wkh[KVH * HID],  g_wkl[KVH * HID];
__device__ bf16 g_wvh[KVH * HID],  g_wvl[KVH * HID];
__device__ bf16 g_woh[HID * HID],  g_wol[HID * HID];
__device__ bf16 g_qh[S_LEN * HID], g_ql[S_LEN * HID];
__device__ bf16 g_kh[S_LEN * KVH], g_kl[S_LEN * KVH];
__device__ bf16 g_vh[S_LEN * KVH], g_vl[S_LEN * KVH];
__device__ bf16 g_oh[S_LEN * HID], g_ol[S_LEN * HID];

__device__ __forceinline__ uint32_t smem_u32(const void* p) {
    return (uint32_t)__cvta_generic_to_shared(p);
}

#define MMA_BF16(c, a0, a1, a2, a3, b0, b1)                                 \
    asm("mma.sync.aligned.m16n8k16.row.col.f32.bf16.bf16.f32 "              \
        "{%0,%1,%2,%3},{%4,%5,%6,%7},{%8,%9},{%0,%1,%2,%3};"                \
        : "+f"(c[0]), "+f"(c[1]), "+f"(c[2]), "+f"(c[3])                    \
        : "r"(a0), "r"(a1), "r"(a2), "r"(a3), "r"(b0), "r"(b1))

#define LDSM_X4(r0, r1, r2, r3, addr)                                       \
    asm("ldmatrix.sync.aligned.m8n8.x4.shared.b16 {%0,%1,%2,%3},[%4];"      \
        : "=r"(r0), "=r"(r1), "=r"(r2), "=r"(r3) : "r"(addr))

#define LDSM_X2(r0, r1, addr)                                               \
    asm("ldmatrix.sync.aligned.m8n8.x2.shared.b16 {%0,%1},[%2];"            \
        : "=r"(r0), "=r"(r1) : "r"(addr))

#define LDSM_X2T(r0, r1, addr)                                              \
    asm("ldmatrix.sync.aligned.m8n8.x2.trans.shared.b16 {%0,%1},[%2];"      \
        : "=r"(r0), "=r"(r1) : "r"(addr))

#define CP_ASYNC16(dst, src)                                                \
    asm volatile("cp.async.cg.shared.global [%0],[%1],16;"                  \
                 :: "r"(dst), "l"(src))
#define CP_COMMIT  asm volatile("cp.async.commit_group;" ::: "memory")
#define CP_WAIT(n) asm volatile("cp.async.wait_group %0;" :: "n"(n) : "memory")

__device__ __forceinline__ uint32_t pack2_hi(float x, float y) {
    __nv_bfloat162 t;
    t.x = __float2bfloat16(x); t.y = __float2bfloat16(y);
    return *(uint32_t*)&t;
}
__device__ __forceinline__ uint32_t pack2_lo(float x, float y) {
    __nv_bfloat162 t;
    t.x = __float2bfloat16(x - __bfloat162float(__float2bfloat16(x)));
    t.y = __float2bfloat16(y - __bfloat162float(__float2bfloat16(y)));
    return *(uint32_t*)&t;
}

// ---------------------------------------------------------------------------
// f32 -> (hi, lo) bf16 plane split (one-shot, memory bound)
// ---------------------------------------------------------------------------
__global__ void split_f32(const float* __restrict__ in,
                          bf16* __restrict__ hi, bf16* __restrict__ lo, int n4)
{
    int i = blockIdx.x * blockDim.x + threadIdx.x;
    if (i >= n4) return;
    float4 v = ((const float4*)in)[i];
    ((uint32_t*)hi)[i * 2]     = pack2_hi(v.x, v.y);
    ((uint32_t*)hi)[i * 2 + 1] = pack2_hi(v.z, v.w);
    ((uint32_t*)lo)[i * 2]     = pack2_lo(v.x, v.y);
    ((uint32_t*)lo)[i * 2 + 1] = pack2_lo(v.z, v.w);
}

// ---------------------------------------------------------------------------
// GEMM core: C[M,N] = A @ B^T (+bias). bf16 planes in, 3-term MMA.
// 128x128 tile, BK=32, double-buffered cp.async smem, 8 warps (2Mx4N).
// ---------------------------------------------------------------------------
#define PLANE_B 10240          // 128 rows * 40 elems * 2B
#define BUF_B   40960          // 4 planes
#define GSMEM   81920          // 2 buffers

__device__ __forceinline__ void gemm_prefetch(
    uint32_t s_base, int buf,
    const bf16* __restrict__ Ahg, const bf16* __restrict__ Alg,
    const bf16* __restrict__ Bhg, const bf16* __restrict__ Blg,
    int bm, int bn, int K, int k0, int tid)
{
#pragma unroll
    for (int j = 0; j < 8; j++) {
        const int plane = j >> 1;
        const int t = tid * 2 + (j & 1);     // 0..511
        const int r = t >> 2, c8 = t & 3;
        const bf16* src = (plane == 0) ? Ahg : (plane == 1) ? Alg
                        : (plane == 2) ? Bhg : Blg;
        const int rowbase = (plane < 2) ? bm : bn;
        uint32_t dst = s_base + (uint32_t)buf * BUF_B + (uint32_t)plane * PLANE_B
                     + (uint32_t)(r * 40 + c8 * 8) * 2;
        CP_ASYNC16(dst, src + (size_t)(rowbase + r) * K + k0 + c8 * 8);
    }
}

__device__ __forceinline__ void gemm_core(
    const bf16* __restrict__ Ahg, const bf16* __restrict__ Alg,
    const bf16* __restrict__ Bhg, const bf16* __restrict__ Blg,
    const float* __restrict__ bias,
    bf16* __restrict__ Ch, bf16* __restrict__ Cl, float* __restrict__ Cf,
    int bm, int bn, int N, int K)
{
    extern __shared__ bf16 smbuf[];
    const uint32_t s_base = smem_u32(smbuf);
    const int tid  = threadIdx.x, warp = tid >> 5, lane = tid & 31;
    const int wm   = (warp & 1) * 64, wn = (warp >> 1) * 32;
    const int g    = lane >> 2, t2 = (lane & 3) * 2;
    const int arow = (lane & 7) + ((lane & 8) ? 8 : 0);
    const int brow = lane & 7;

    float acc[4][4][4];
#pragma unroll
    for (int mi = 0; mi < 4; mi++)
#pragma unroll
        for (int ni = 0; ni < 4; ni++)
#pragma unroll
            for (int q = 0; q < 4; q++) acc[mi][ni][q] = 0.f;

    const int nchunk = K >> 5;
    gemm_prefetch(s_base, 0, Ahg, Alg, Bhg, Blg, bm, bn, K, 0, tid);
    CP_COMMIT;

    for (int c = 0; c < nchunk; c++) {
        if (c + 1 < nchunk) {
            gemm_prefetch(s_base, (c + 1) & 1, Ahg, Alg, Bhg, Blg,
                          bm, bn, K, (c + 1) << 5, tid);
            CP_COMMIT;
            CP_WAIT(1);
        } else {
            CP_WAIT(0);
        }
        __syncthreads();

        const uint32_t bufb = s_base + (uint32_t)(c & 1) * BUF_B;
        const uint32_t aAh = bufb, aAl = bufb + PLANE_B;
        const uint32_t aBh = bufb + 2 * PLANE_B, aBl = bufb + 3 * PLANE_B;

#pragma unroll
        for (int kt = 0; kt < 32; kt += 16) {
            const int acol = kt + ((lane & 16) ? 8 : 0);
            uint32_t ah[4][4], al[4][4];
#pragma unroll
            for (int mi = 0; mi < 4; mi++) {
                const uint32_t off = (uint32_t)((wm + mi * 16 + arow) * 40 + acol) * 2;
                LDSM_X4(ah[mi][0], ah[mi][1], ah[mi][2], ah[mi][3], aAh + off);
                LDSM_X4(al[mi][0], al[mi][1], al[mi][2], al[mi][3], aAl + off);
            }
            const int bcol = kt + ((lane & 8) ? 8 : 0);
#pragma unroll
            for (int ni = 0; ni < 4; ni++) {
                const uint32_t boff = (uint32_t)((wn + ni * 8 + brow) * 40 + bcol) * 2;
                uint32_t bh0, bh1, bl0, bl1;
                LDSM_X2(bh0, bh1, aBh + boff);
                LDSM_X2(bl0, bl1, aBl + boff);
#pragma unroll
                for (int mi = 0; mi < 4; mi++) {
                    MMA_BF16(acc[mi][ni], ah[mi][0], ah[mi][1], ah[mi][2], ah[mi][3], bh0, bh1);
                    MMA_BF16(acc[mi][ni], ah[mi][0], ah[mi][1], ah[mi][2], ah[mi][3], bl0, bl1);
                    MMA_BF16(acc[mi][ni], al[mi][0], al[mi][1], al[mi][2], al[mi][3], bh0, bh1);
                }
            }
        }
        __syncthreads();
    }

#pragma unroll
    for (int mi = 0; mi < 4; mi++) {
#pragma unroll
        for (int ni = 0; ni < 4; ni++) {
            const int row = bm + wm + mi * 16 + g;
            const int col = bn + wn + ni * 8 + t2;
            float b0 = bias ? bias[col] : 0.f;
            float b1 = bias ? bias[col + 1] : 0.f;
            float v0 = acc[mi][ni][0] + b0, v1 = acc[mi][ni][1] + b1;
            float v2 = acc[mi][ni][2] + b0, v3 = acc[mi][ni][3] + b1;
            if (Cf) {
                float2 w0; w0.x = v0; w0.y = v1;
                float2 w1; w1.x = v2; w1.y = v3;
                *(float2*)&Cf[(size_t)row * N + col]       = w0;
                *(float2*)&Cf[(size_t)(row + 8) * N + col] = w1;
            } else {
                *(uint32_t*)&Ch[(size_t)row * N + col]       = pack2_hi(v0, v1);
                *(uint32_t*)&Cl[(size_t)row * N + col]       = pack2_lo(v0, v1);
                *(uint32_t*)&Ch[(size_t)(row + 8) * N + col] = pack2_hi(v2, v3);
                *(uint32_t*)&Cl[(size_t)(row + 8) * N + col] = pack2_lo(v2, v3);
            }
        }
    }
}

// Fused QKV projection: blockIdx.x 0..15 -> Q, 16..19 -> K, 20..23 -> V
__global__ __launch_bounds__(256) void qkv_gemm(
    const float* __restrict__ bq, const float* __restrict__ bk,
    const float* __restrict__ bv)
{
    const int bx = blockIdx.x, bm = blockIdx.y * 128;
    const bf16 *Bh, *Bl; const float* bias; bf16 *Ch, *Cl; int N, bn;
    if (bx < 16)      { Bh = g_wqh; Bl = g_wql; bias = bq; Ch = g_qh; Cl = g_ql; N = HID; bn = bx * 128; }
    else if (bx < 20) { Bh = g_wkh; Bl = g_wkl; bias = bk; Ch = g_kh; Cl = g_kl; N = KVH; bn = (bx - 16) * 128; }
    else              { Bh = g_wvh; Bl = g_wvl; bias = bv; Ch = g_vh; Cl = g_vl; N = KVH; bn = (bx - 20) * 128; }
    gemm_core(g_xh, g_xl, Bh, Bl, bias, Ch, Cl, nullptr, bm, bn, N, HID);
}

__global__ __launch_bounds__(256) void o_gemm(float* __restrict__ out)
{
    gemm_core(g_oh, g_ol, g_woh, g_wol, nullptr, nullptr, nullptr, out,
              blockIdx.y * 128, blockIdx.x * 128, HID, HID);
}

// ---------------------------------------------------------------------------
// RoPE in-place on split planes (position_ids are int32)
// ---------------------------------------------------------------------------
__global__ void rope_sp(bf16* __restrict__ hi, bf16* __restrict__ lo,
                        const int* __restrict__ pos_ids,
                        int nheads, int stride, int total)
{
    int idx = blockIdx.x * blockDim.x + threadIdx.x;
    if (idx >= total) return;
    int i = idx & 63;
    int h = (idx >> 6) % nheads;
    int s = idx / (64 * nheads);

    float pos = (float)pos_ids[s];
    float inv = expf(-(float)(2 * i) * (1.0f / 128.0f) * 9.210340371976184f);
    float ang = pos * inv;
    float c, sn;
    sincosf(ang, &sn, &c);

    size_t base = (size_t)s * stride + h * HD;
    float x0 = __bfloat162float(hi[base + i])      + __bfloat162float(lo[base + i]);
    float x1 = __bfloat162float(hi[base + i + 64]) + __bfloat162float(lo[base + i + 64]);
    float y0 = x0 * c - x1 * sn;
    float y1 = x1 * c + x0 * sn;
    bf16 h0 = __float2bfloat16(y0);
    bf16 h1 = __float2bfloat16(y1);
    hi[base + i]      = h0;
    lo[base + i]      = __float2bfloat16(y0 - __bfloat162float(h0));
    hi[base + i + 64] = h1;
    lo[base + i + 64] = __float2bfloat16(y1 - __bfloat162float(h1));
}

// ---------------------------------------------------------------------------
// Flash attention, warp-mma, bf16-split planes in/out. Causal, GQA 4:1.
// Block: 128 q-rows x one head, 256 threads (8 warps x 16 rows), KV tile 64.
// ---------------------------------------------------------------------------
#define FLQ 136
#define FSMEM ((2 * 128 * FLQ + 4 * 64 * FLQ) * 2)   // 139264 bytes

__global__ __launch_bounds__(256) void flash_sp()
{
    extern __shared__ bf16 sm[];
    bf16* Qh = sm;
    bf16* Ql = Qh + 128 * FLQ;
    bf16* Kh = Ql + 128 * FLQ;
    bf16* Kl = Kh + 64 * FLQ;
    bf16* Vh = Kl + 64 * FLQ;
    bf16* Vl = Vh + 64 * FLQ;
    const uint32_t aQh = smem_u32(Qh), aQl = smem_u32(Ql);
    const uint32_t aKh = smem_u32(Kh), aKl = smem_u32(Kl);
    const uint32_t aVh = smem_u32(Vh), aVl = smem_u32(Vl);

    const int h   = blockIdx.y;
    const int qt  = blockIdx.x;
    const int q0  = qt * 128;
    const int kvh = h >> 2;
    const int tid = threadIdx.x, warp = tid >> 5, lane = tid & 31;
    const int g   = lane >> 2, t2 = (lane & 3) * 2;

    // Q tile via cp.async (2 planes, 128x128)
#pragma unroll
    for (int j = 0; j < 16; j++) {
        const int plane = j >> 3;
        const int t = tid * 8 + (j & 7);           // 0..2047
        const int r = t >> 4, c16 = t & 15;
        const bf16* src = (plane ? g_ql : g_qh) + (size_t)(q0 + r) * HID + h * HD + c16 * 8;
        uint32_t dst = (plane ? aQl : aQh) + (uint32_t)(r * FLQ + c16 * 8) * 2;
        CP_ASYNC16(dst, src);
    }
    CP_COMMIT;

    float m0 = -1e30f, m1 = -1e30f, l0 = 0.f, l1 = 0.f;
    float oacc[16][4];
#pragma unroll
    for (int nf = 0; nf < 16; nf++)
#pragma unroll
        for (int q = 0; q < 4; q++) oacc[nf][q] = 0.f;

    const float scale = 0.08838834764831845f;
    const int mrow = warp * 16;
    const int r0 = q0 + mrow + g, r1 = r0 + 8;
    const int wmax = q0 + mrow + 15;
    const int arow = (lane & 7) + ((lane & 8) ? 8 : 0);
    const int brow = lane & 7;
    const int vrow = lane & 15;

    const int ntiles = 2 * qt + 2;
    for (int t = 0; t < ntiles; t++) {
        const int j0 = t * 64;
        __syncthreads();
        // KV tile via cp.async (4 planes, 64x128 each)
#pragma unroll
        for (int j = 0; j < 16; j++) {
            const int plane = j >> 2;
            const int tt = tid * 4 + (j & 3);      // 0..1023
            const int r = tt >> 4, c16 = tt & 15;
            const bf16* src;
            uint32_t dstb;
            if (plane == 0)      { src = g_kh; dstb = aKh; }
            else if (plane == 1) { src = g_kl; dstb = aKl; }
            else if (plane == 2) { src = g_vh; dstb = aVh; }
            else                 { src = g_vl; dstb = aVl; }
            src += (size_t)(j0 + r) * KVH + kvh * HD + c16 * 8;
            CP_ASYNC16(dstb + (uint32_t)(r * FLQ + c16 * 8) * 2, src);
        }
        CP_COMMIT;
        CP_WAIT(0);
        __syncthreads();
        if (j0 > wmax) continue;

        // ---- S = Q K^T ----
        float s[8][4];
#pragma unroll
        for (int nf = 0; nf < 8; nf++)
#pragma unroll
            for (int q = 0; q < 4; q++) s[nf][q] = 0.f;

#pragma unroll
        for (int kt = 0; kt < 128; kt += 16) {
            const int acol = kt + ((lane & 16) ? 8 : 0);
            uint32_t qh[4], ql[4];
            LDSM_X4(qh[0], qh[1], qh[2], qh[3], smem_u32(&Qh[(mrow + arow) * FLQ + acol]));
            LDSM_X4(ql[0], ql[1], ql[2], ql[3], smem_u32(&Ql[(mrow + arow) * FLQ + acol]));
            const int bcol = kt + ((lane & 8) ? 8 : 0);
#pragma unroll
            for (int nf = 0; nf < 8; nf++) {
                uint32_t bh0, bh1, bl0, bl1;
                LDSM_X2(bh0, bh1, smem_u32(&Kh[(nf * 8 + brow) * FLQ + bcol]));
                LDSM_X2(bl0, bl1, smem_u32(&Kl[(nf * 8 + brow) * FLQ + bcol]));
                MMA_BF16(s[nf], qh[0], qh[1], qh[2], qh[3], bh0, bh1);
                MMA_BF16(s[nf], qh[0], qh[1], qh[2], qh[3], bl0, bl1);
                MMA_BF16(s[nf], ql[0], ql[1], ql[2], ql[3], bh0, bh1);
            }
        }

#pragma unroll
        for (int nf = 0; nf < 8; nf++)
#pragma unroll
            for (int q = 0; q < 4; q++) s[nf][q] *= scale;

        if (j0 + 63 > r0) {
#pragma unroll
            for (int nf = 0; nf < 8; nf++) {
                const int c0 = j0 + nf * 8 + t2;
                if (c0     > r0) s[nf][0] = -1e30f;
                if (c0 + 1 > r0) s[nf][1] = -1e30f;
                if (c0     > r1) s[nf][2] = -1e30f;
                if (c0 + 1 > r1) s[nf][3] = -1e30f;
            }
        }

        // ---- online softmax ----
        float mx0 = -1e30f, mx1 = -1e30f;
#pragma unroll
        for (int nf = 0; nf < 8; nf++) {
            mx0 = fmaxf(mx0, fmaxf(s[nf][0], s[nf][1]));
            mx1 = fmaxf(mx1, fmaxf(s[nf][2], s[nf][3]));
        }
        mx0 = fmaxf(mx0, __shfl_xor_sync(0xffffffffu, mx0, 1));
        mx0 = fmaxf(mx0, __shfl_xor_sync(0xffffffffu, mx0, 2));
        mx1 = fmaxf(mx1, __shfl_xor_sync(0xffffffffu, mx1, 1));
        mx1 = fmaxf(mx1, __shfl_xor_sync(0xffffffffu, mx1, 2));
        const float mn0 = fmaxf(m0, mx0), mn1 = fmaxf(m1, mx1);
        const float a0 = __expf(m0 - mn0), a1 = __expf(m1 - mn1);
        float sum0 = 0.f, sum1 = 0.f;
#pragma unroll
        for (int nf = 0; nf < 8; nf++) {
            s[nf][0] = __expf(s[nf][0] - mn0);
            s[nf][1] = __expf(s[nf][1] - mn0);
            s[nf][2] = __expf(s[nf][2] - mn1);
            s[nf][3] = __expf(s[nf][3] - mn1);
            sum0 += s[nf][0] + s[nf][1];
            sum1 += s[nf][2] + s[nf][3];
        }
        sum0 += __shfl_xor_sync(0xffffffffu, sum0, 1);
        sum0 += __shfl_xor_sync(0xffffffffu, sum0, 2);
        sum1 += __shfl_xor_sync(0xffffffffu, sum1, 1);
        sum1 += __shfl_xor_sync(0xffffffffu, sum1, 2);
        l0 = l0 * a0 + sum0;  l1 = l1 * a1 + sum1;
        m0 = mn0;             m1 = mn1;
#pragma unroll
        for (int nf = 0; nf < 16; nf++) {
            oacc[nf][0] *= a0; oacc[nf][1] *= a0;
            oacc[nf][2] *= a1; oacc[nf][3] *= a1;
        }

        // ---- pack P fragments ----
        uint32_t pah[4][4], pal[4][4];
#pragma unroll
        for (int j = 0; j < 4; j++) {
            pah[j][0] = pack2_hi(s[2*j][0],   s[2*j][1]);
            pah[j][1] = pack2_hi(s[2*j][2],   s[2*j][3]);
            pah[j][2] = pack2_hi(s[2*j+1][0], s[2*j+1][1]);
            pah[j][3] = pack2_hi(s[2*j+1][2], s[2*j+1][3]);
            pal[j][0] = pack2_lo(s[2*j][0],   s[2*j][1]);
            pal[j][1] = pack2_lo(s[2*j][2],   s[2*j][3]);
            pal[j][2] = pack2_lo(s[2*j+1][0], s[2*j+1][1]);
            pal[j][3] = pack2_lo(s[2*j+1][2], s[2*j+1][3]);
        }

        // ---- O += P @ V ----
#pragma unroll
        for (int j = 0; j < 4; j++) {
#pragma unroll
            for (int nf = 0; nf < 16; nf++) {
                uint32_t bh0, bh1, bl0, bl1;
                LDSM_X2T(bh0, bh1, smem_u32(&Vh[(16 * j + vrow) * FLQ + nf * 8]));
                LDSM_X2T(bl0, bl1, smem_u32(&Vl[(16 * j + vrow) * FLQ + nf * 8]));
                MMA_BF16(oacc[nf], pah[j][0], pah[j][1], pah[j][2], pah[j][3], bh0, bh1);
                MMA_BF16(oacc[nf], pah[j][0], pah[j][1], pah[j][2], pah[j][3], bl0, bl1);
                MMA_BF16(oacc[nf], pal[j][0], pal[j][1], pal[j][2], pal[j][3], bh0, bh1);
            }
        }
    }

    // ---- normalize + store split planes ----
    const float inv0 = 1.f / l0, inv1 = 1.f / l1;
#pragma unroll
    for (int nf = 0; nf < 16; nf++) {
        const int col = h * HD + nf * 8 + t2;
        float v0 = oacc[nf][0] * inv0, v1 = oacc[nf][1] * inv0;
        float v2 = oacc[nf][2] * inv1, v3 = oacc[nf][3] * inv1;
        *(uint32_t*)&g_oh[(size_t)r0 * HID + col] = pack2_hi(v0, v1);
        *(uint32_t*)&g_ol[(size_t)r0 * HID + col] = pack2_lo(v0, v1);
        *(uint32_t*)&g_oh[(size_t)r1 * HID + col] = pack2_hi(v2, v3);
        *(uint32_t*)&g_ol[(size_t)r1 * HID + col] = pack2_lo(v2, v3);
    }
}

// ---------------------------------------------------------------------------

extern "C" void kernel_launch(void* const* d_in, const int* in_sizes, int n_in,
                              void* d_out, int out_size)
{
    const float* x   = (const float*)d_in[0];
    /* d_in[1] attention_mask: exact causal triu(-inf), applied analytically */
    const int*   pos = (const int*)d_in[2];
    const float* wq  = (const float*)d_in[3];
    const float* bq  = (const float*)d_in[4];
    const float* wk  = (const float*)d_in[5];
    const float* bk  = (const float*)d_in[6];
    const float* wv  = (const float*)d_in[7];
    const float* bv  = (const float*)d_in[8];
    const float* wo  = (const float*)d_in[9];
    float*       out = (float*)d_out;

    bf16 *xh, *xl, *wqh, *wql, *wkh, *wkl, *wvh, *wvl, *woh, *wol;
    bf16 *qh, *ql, *kh, *kl;
    cudaGetSymbolAddress((void**)&xh,  g_xh);  cudaGetSymbolAddress((void**)&xl,  g_xl);
    cudaGetSymbolAddress((void**)&wqh, g_wqh); cudaGetSymbolAddress((void**)&wql, g_wql);
    cudaGetSymbolAddress((void**)&wkh, g_wkh); cudaGetSymbolAddress((void**)&wkl, g_wkl);
    cudaGetSymbolAddress((void**)&wvh, g_wvh); cudaGetSymbolAddress((void**)&wvl, g_wvl);
    cudaGetSymbolAddress((void**)&woh, g_woh); cudaGetSymbolAddress((void**)&wol, g_wol);
    cudaGetSymbolAddress((void**)&qh,  g_qh);  cudaGetSymbolAddress((void**)&ql,  g_ql);
    cudaGetSymbolAddress((void**)&kh,  g_kh);  cudaGetSymbolAddress((void**)&kl,  g_kl);

    cudaFuncSetAttribute(qkv_gemm, cudaFuncAttributeMaxDynamicSharedMemorySize, GSMEM);
    cudaFuncSetAttribute(o_gemm,   cudaFuncAttributeMaxDynamicSharedMemorySize, GSMEM);
    cudaFuncSetAttribute(flash_sp, cudaFuncAttributeMaxDynamicSharedMemorySize, FSMEM);

    // one-shot splits (memory bound)
    split_f32<<<(S_LEN * HID / 4 + 255) / 256, 256>>>(x,  xh,  xl,  S_LEN * HID / 4);
    split_f32<<<(HID * HID / 4 + 255) / 256, 256>>>(wq, wqh, wql, HID * HID / 4);
    split_f32<<<(KVH * HID / 4 + 255) / 256, 256>>>(wk, wkh, wkl, KVH * HID / 4);
    split_f32<<<(KVH * HID / 4 + 255) / 256, 256>>>(wv, wvh, wvl, KVH * HID / 4);
    split_f32<<<(HID * HID / 4 + 255) / 256, 256>>>(wo, woh, wol, HID * HID / 4);

    // fused QKV projection
    qkv_gemm<<<dim3(24, 16), 256, GSMEM>>>(bq, bk, bv);

    // RoPE on split planes
    {
        int totq = S_LEN * NH * 64;
        rope_sp<<<(totq + 255) / 256, 256>>>(qh, ql, pos, NH, HID, totq);
        int totk = S_LEN * NKV * 64;
        rope_sp<<<(totk + 255) / 256, 256>>>(kh, kl, pos, NKV, KVH, totk);
    }

    // flash attention
    flash_sp<<<dim3(S_LEN / 128, NH), 256, FSMEM>>>();

    // output projection -> fp32
    o_gemm<<<dim3(HID / 128, S_LEN / 128), 256, GSMEM>>>(out);
}